// round 3
// baseline (speedup 1.0000x reference)
#include <cuda_runtime.h>

#define H 1024
#define S 65536
#define RPB 8                       // rows per block in GEMV (1 row per warp)
#define GEMV_GRID (S / RPB)         // 8192 blocks
#define EXP_BLOCKS 256
#define EXP_TPB 256                 // 256*256 = 65536

// ---- scratch (device globals; no allocation anywhere) ----
__device__ float g_vpart[16 * H];       // split-i partials of v = W^T h
__device__ float g_v[H];                // reduced v
__device__ float g_bh;                  // b . h
__device__ float g_scores[S];           // raw scores
__device__ float g_bmax[GEMV_GRID];     // per-block max of scores
__device__ float g_gmax;                // global max
__device__ float g_bsum[EXP_BLOCKS];    // per-block exp sums
__device__ float g_inv;                 // 1 / total sum

// K1: partial v[j] = sum_{i in chunk} W[i][j]*h[i]  (64 blocks),
//     plus one extra block computing b.h
__global__ void k1_prep(const float* __restrict__ hidden,
                        const float* __restrict__ W,
                        const float* __restrict__ b) {
    int blk = blockIdx.x;
    if (blk < 64) {
        int jb = blk & 3;          // which 256-column slab
        int ic = blk >> 2;         // which 64-row chunk of i
        int j  = jb * 256 + threadIdx.x;
        const float* Wp = W + (size_t)ic * 64 * H + j;
        float acc = 0.f;
#pragma unroll
        for (int i = 0; i < 64; i++)
            acc = fmaf(Wp[(size_t)i * H], hidden[ic * 64 + i], acc);
        g_vpart[ic * H + j] = acc;
    } else {
        __shared__ float s[256];
        float acc = 0.f;
        for (int i = threadIdx.x; i < H; i += 256)
            acc = fmaf(b[i], hidden[i], acc);
        s[threadIdx.x] = acc;
        __syncthreads();
        for (int o = 128; o; o >>= 1) {
            if (threadIdx.x < o) s[threadIdx.x] += s[threadIdx.x + o];
            __syncthreads();
        }
        if (threadIdx.x == 0) g_bh = s[0];
    }
}

// K1b: reduce the 16 i-chunk partials -> g_v
__global__ void k1b_reduce_v() {
    int j = threadIdx.x;            // 1024 threads
    float acc = 0.f;
#pragma unroll
    for (int c = 0; c < 16; c++) acc += g_vpart[c * H + j];
    g_v[j] = acc;
}

// K2: scores[r] = enc[r] . v + bh ; per-block max -> g_bmax
// 1 warp per row, float4 loads, v staged in shared as float4 (LDS.128, conflict-free)
__global__ __launch_bounds__(256) void k2_gemv(const float* __restrict__ enc) {
    __shared__ float4 sv[H / 4];    // 256 float4 = 4KB
    sv[threadIdx.x] = ((const float4*)g_v)[threadIdx.x];
    __syncthreads();

    int warp = threadIdx.x >> 5;
    int lane = threadIdx.x & 31;
    int row  = blockIdx.x * RPB + warp;
    const float4* rp = (const float4*)(enc + (size_t)row * H);

    float4 a[8];
#pragma unroll
    for (int k = 0; k < 8; k++) a[k] = rp[lane + 32 * k];   // front-batched, MLP=8

    float acc = 0.f;
#pragma unroll
    for (int k = 0; k < 8; k++) {
        float4 vv = sv[lane + 32 * k];
        acc = fmaf(a[k].x, vv.x, acc);
        acc = fmaf(a[k].y, vv.y, acc);
        acc = fmaf(a[k].z, vv.z, acc);
        acc = fmaf(a[k].w, vv.w, acc);
    }
#pragma unroll
    for (int o = 16; o; o >>= 1) acc += __shfl_xor_sync(0xFFFFFFFFu, acc, o);

    __shared__ float ws[RPB];
    if (lane == 0) {
        float sc = acc + g_bh;
        g_scores[row] = sc;
        ws[warp] = sc;
    }
    __syncthreads();
    if (threadIdx.x == 0) {
        float m = ws[0];
#pragma unroll
        for (int i = 1; i < RPB; i++) m = fmaxf(m, ws[i]);
        g_bmax[blockIdx.x] = m;
    }
}

// K3: reduce 8192 block maxes -> g_gmax  (one block, 1024 threads)
__global__ void k3_max() {
    __shared__ float s[1024];
    float m = -3.4e38f;
#pragma unroll
    for (int k = 0; k < GEMV_GRID / 1024; k++)
        m = fmaxf(m, g_bmax[k * 1024 + threadIdx.x]);
    s[threadIdx.x] = m;
    __syncthreads();
    for (int o = 512; o; o >>= 1) {
        if (threadIdx.x < o) s[threadIdx.x] = fmaxf(s[threadIdx.x], s[threadIdx.x + o]);
        __syncthreads();
    }
    if (threadIdx.x == 0) g_gmax = s[0];
}

// K4: out[i] = exp(scores[i] - gmax); per-block sums -> g_bsum
__global__ void k4_exp(float* __restrict__ out) {
    __shared__ float s[EXP_TPB];
    int i = blockIdx.x * EXP_TPB + threadIdx.x;
    float e = expf(g_scores[i] - g_gmax);
    out[i] = e;
    s[threadIdx.x] = e;
    __syncthreads();
    for (int o = EXP_TPB / 2; o; o >>= 1) {
        if (threadIdx.x < o) s[threadIdx.x] += s[threadIdx.x + o];
        __syncthreads();
    }
    if (threadIdx.x == 0) g_bsum[blockIdx.x] = s[0];
}

// K5: total sum -> g_inv (one block, 256 threads)
__global__ void k5_sum() {
    __shared__ float s[EXP_BLOCKS];
    s[threadIdx.x] = g_bsum[threadIdx.x];
    __syncthreads();
    for (int o = EXP_BLOCKS / 2; o; o >>= 1) {
        if (threadIdx.x < o) s[threadIdx.x] += s[threadIdx.x + o];
        __syncthreads();
    }
    if (threadIdx.x == 0) g_inv = 1.0f / s[0];
}

// K6: normalize
__global__ void k6_scale(float* __restrict__ out) {
    int i = blockIdx.x * EXP_TPB + threadIdx.x;
    out[i] *= g_inv;
}

extern "C" void kernel_launch(void* const* d_in, const int* in_sizes, int n_in,
                              void* d_out, int out_size) {
    const float* hidden = (const float*)d_in[0];   // [1024]
    const float* enc    = (const float*)d_in[1];   // [65536, 1024]
    const float* W      = (const float*)d_in[2];   // [1024, 1024]
    const float* b      = (const float*)d_in[3];   // [1024]
    float* out = (float*)d_out;                    // [65536]

    k1_prep<<<65, 256>>>(hidden, W, b);
    k1b_reduce_v<<<1, 1024>>>();
    k2_gemv<<<GEMV_GRID, 256>>>(enc);
    k3_max<<<1, 1024>>>();
    k4_exp<<<EXP_BLOCKS, EXP_TPB>>>(out);
    k5_sum<<<1, EXP_BLOCKS>>>();
    k6_scale<<<EXP_BLOCKS, EXP_TPB>>>(out);
}

// round 4
// speedup vs baseline: 1.1126x; 1.1126x over previous
#include <cuda_runtime.h>

#define H 1024
#define S 65536
#define RPB 8                       // rows per block in GEMV (1 row per warp)
#define GEMV_GRID (S / RPB)         // 8192 blocks
#define IC 32                       // i-chunks in k1 (32 rows each)
#define K1_GRID (IC * 4 + 1)        // 129 blocks
#define FIN_BLOCKS 256
#define FIN_TPB 256

// ---- scratch (device globals; no allocation anywhere) ----
__device__ float g_vpart[IC * H];       // split-i partials of v = W^T h
__device__ float g_v[H];                // reduced v
__device__ float g_bh;                  // b . h
__device__ float g_bm[GEMV_GRID];       // per-block score max
__device__ float g_bs[GEMV_GRID];       // per-block sum of exp(s - m_b)
__device__ unsigned g_ctr1;             // last-block counter for k1 (self-resetting)

// ---------------------------------------------------------------------------
// K1: partial v[j] = sum_{i in chunk} W[i][j]*h[i]  (128 blocks, 32 rows each)
//     + one block for b.h ; last finished block reduces partials -> g_v
// ---------------------------------------------------------------------------
__global__ __launch_bounds__(256) void k1_prep(const float* __restrict__ hidden,
                                               const float* __restrict__ W,
                                               const float* __restrict__ b) {
    int blk = blockIdx.x;
    if (blk < IC * 4) {
        int jb = blk & 3;          // which 256-column slab
        int ic = blk >> 2;         // which 32-row chunk of i
        int j  = jb * 256 + threadIdx.x;
        const float* Wp = W + (size_t)ic * 32 * H + j;
        float acc = 0.f;
#pragma unroll
        for (int i = 0; i < 32; i++)
            acc = fmaf(Wp[(size_t)i * H], hidden[ic * 32 + i], acc);
        g_vpart[ic * H + j] = acc;
    } else {
        __shared__ float s[256];
        float acc = 0.f;
        for (int i = threadIdx.x; i < H; i += 256)
            acc = fmaf(b[i], hidden[i], acc);
        s[threadIdx.x] = acc;
        __syncthreads();
        for (int o = 128; o; o >>= 1) {
            if (threadIdx.x < o) s[threadIdx.x] += s[threadIdx.x + o];
            __syncthreads();
        }
        if (threadIdx.x == 0) g_bh = s[0];
    }

    // last-block-done: fold the partial reduction into this launch
    __threadfence();
    __shared__ bool isLast;
    if (threadIdx.x == 0) {
        unsigned t = atomicAdd(&g_ctr1, 1u);
        isLast = (t == K1_GRID - 1);
        if (isLast) g_ctr1 = 0;    // reset for next graph replay
    }
    __syncthreads();
    if (isLast) {
        __threadfence();
#pragma unroll
        for (int r = 0; r < H / 256; r++) {     // 4 j's per thread
            int j = r * 256 + threadIdx.x;
            float acc = 0.f;
#pragma unroll
            for (int c = 0; c < IC; c++) acc += g_vpart[c * H + j];
            g_v[j] = acc;
        }
    }
}

// ---------------------------------------------------------------------------
// K2: streaming GEMV + partial softmax.
// 1 warp per row, 8x front-batched LDG.128 (evict-first), v staged in shared.
// Per block: out[row] = exp(score - m_b); store (m_b, sum_b).
// ---------------------------------------------------------------------------
__global__ __launch_bounds__(256) void k2_gemv(const float* __restrict__ enc,
                                               float* __restrict__ out) {
    __shared__ float4 sv[H / 4];    // 256 float4 = 4KB
    sv[threadIdx.x] = ((const float4*)g_v)[threadIdx.x];
    __syncthreads();

    int warp = threadIdx.x >> 5;
    int lane = threadIdx.x & 31;
    int row  = blockIdx.x * RPB + warp;
    const float4* rp = (const float4*)(enc + (size_t)row * H);

    float4 a[8];
#pragma unroll
    for (int k = 0; k < 8; k++) a[k] = __ldcs(rp + lane + 32 * k);  // MLP=8

    float acc = 0.f;
#pragma unroll
    for (int k = 0; k < 8; k++) {
        float4 vv = sv[lane + 32 * k];
        acc = fmaf(a[k].x, vv.x, acc);
        acc = fmaf(a[k].y, vv.y, acc);
        acc = fmaf(a[k].z, vv.z, acc);
        acc = fmaf(a[k].w, vv.w, acc);
    }
#pragma unroll
    for (int o = 16; o; o >>= 1) acc += __shfl_xor_sync(0xFFFFFFFFu, acc, o);

    __shared__ float ws[RPB];
    if (lane == 0) ws[warp] = acc + g_bh;
    __syncthreads();

    if (threadIdx.x == 0) {
        float mb = ws[0];
#pragma unroll
        for (int i = 1; i < RPB; i++) mb = fmaxf(mb, ws[i]);
        float sm = 0.f;
#pragma unroll
        for (int i = 0; i < RPB; i++) {
            float e = expf(ws[i] - mb);
            sm += e;
            out[blockIdx.x * RPB + i] = e;
        }
        g_bm[blockIdx.x] = mb;
        g_bs[blockIdx.x] = sm;
    }
}

// ---------------------------------------------------------------------------
// K3: finalize. Each block redundantly reduces the 8192 (m_b, sum_b) pairs
// (L2-resident, fixed order -> deterministic), then rescales its 256 outputs:
//   out[i] *= exp(m_b(i) - gmax) / total
// ---------------------------------------------------------------------------
__global__ __launch_bounds__(FIN_TPB) void k3_finalize(float* __restrict__ out) {
    __shared__ float s[FIN_TPB];
    int t = threadIdx.x;

    // global max over 8192 block maxes
    float m = -3.4e38f;
#pragma unroll
    for (int k = 0; k < GEMV_GRID / FIN_TPB; k++)
        m = fmaxf(m, g_bm[t + FIN_TPB * k]);
    s[t] = m;
    __syncthreads();
    for (int o = FIN_TPB / 2; o; o >>= 1) {
        if (t < o) s[t] = fmaxf(s[t], s[t + o]);
        __syncthreads();
    }
    float gmax = s[0];
    __syncthreads();

    // total = sum_b sum_b * exp(m_b - gmax)
    float sm = 0.f;
#pragma unroll
    for (int k = 0; k < GEMV_GRID / FIN_TPB; k++) {
        int idx = t + FIN_TPB * k;
        sm += g_bs[idx] * expf(g_bm[idx] - gmax);
    }
    s[t] = sm;
    __syncthreads();
    for (int o = FIN_TPB / 2; o; o >>= 1) {
        if (t < o) s[t] += s[t + o];
        __syncthreads();
    }
    float inv = 1.0f / s[0];

    // rescale this block's slice of the output
    int i = blockIdx.x * FIN_TPB + t;
    out[i] = out[i] * expf(g_bm[i >> 3] - gmax) * inv;
}

extern "C" void kernel_launch(void* const* d_in, const int* in_sizes, int n_in,
                              void* d_out, int out_size) {
    const float* hidden = (const float*)d_in[0];   // [1024]
    const float* enc    = (const float*)d_in[1];   // [65536, 1024]
    const float* W      = (const float*)d_in[2];   // [1024, 1024]
    const float* b      = (const float*)d_in[3];   // [1024]
    float* out = (float*)d_out;                    // [65536]

    k1_prep<<<K1_GRID, 256>>>(hidden, W, b);
    k2_gemv<<<GEMV_GRID, 256>>>(enc, out);
    k3_finalize<<<FIN_BLOCKS, FIN_TPB>>>(out);
}